// round 4
// baseline (speedup 1.0000x reference)
#include <cuda_runtime.h>

typedef unsigned long long u64;

// Shapes (fixed by the problem)
#define BB 8
#define CC 64
#define HH 32
#define WW 32
#define OO 32
#define QQ 8

// Scratch: sigmoid(x), 8*64*32*32 floats = 2MB (device global, no alloc)
__device__ float g_sig[BB * CC * HH * WW];

__device__ __forceinline__ float sigmoidf(float x) {
    return __fdividef(1.0f, 1.0f + __expf(-x));
}

// ---- packed f32x2 helpers (Blackwell FFMA2 path, PTX-only) ----
__device__ __forceinline__ u64 fma2(u64 a, u64 b, u64 c) {
    u64 d; asm("fma.rn.f32x2 %0, %1, %2, %3;" : "=l"(d) : "l"(a), "l"(b), "l"(c)); return d;
}
__device__ __forceinline__ u64 sub2(u64 a, u64 b) {
    u64 d; asm("sub.rn.f32x2 %0, %1, %2;" : "=l"(d) : "l"(a), "l"(b)); return d;
}
__device__ __forceinline__ u64 pack2(float lo, float hi) {
    u64 r; asm("mov.b64 %0, {%1, %2};" : "=l"(r) : "f"(lo), "f"(hi)); return r;
}
__device__ __forceinline__ float2 unpack2(u64 v) {
    float2 f; asm("mov.b64 {%0, %1}, %2;" : "=f"(f.x), "=f"(f.y) : "l"(v)); return f;
}
__device__ __forceinline__ u64 sig2(u64 v) {
    float2 f = unpack2(v);
    return pack2(sigmoidf(f.x), sigmoidf(f.y));
}

// Packed 4-input multilinear LUT. w: 16 u64 entries, [0..7]=dup(base corners
// bits 0..2), [8..15]=dup(diff = w[j+8]-w[j]). Reduces bit3,2,1,0.
__device__ __forceinline__ u64 lut4p(const u64* __restrict__ w,
                                     u64 x0, u64 x1, u64 x2, u64 x3) {
    u64 v0 = fma2(x3, w[8],  w[0]);
    u64 v1 = fma2(x3, w[9],  w[1]);
    u64 v2 = fma2(x3, w[10], w[2]);
    u64 v3 = fma2(x3, w[11], w[3]);
    u64 v4 = fma2(x3, w[12], w[4]);
    u64 v5 = fma2(x3, w[13], w[5]);
    u64 v6 = fma2(x3, w[14], w[6]);
    u64 v7 = fma2(x3, w[15], w[7]);
    u64 u0 = fma2(x2, sub2(v4, v0), v0);
    u64 u1 = fma2(x2, sub2(v5, v1), v1);
    u64 u2 = fma2(x2, sub2(v6, v2), v2);
    u64 u3 = fma2(x2, sub2(v7, v3), v3);
    u64 t0 = fma2(x1, sub2(u2, u0), u0);
    u64 t1 = fma2(x1, sub2(u3, u1), u1);
    return fma2(x0, sub2(t1, t0), t0);
}

__global__ void sigmoid_kernel(const float* __restrict__ x) {
    int i = blockIdx.x * blockDim.x + threadIdx.x;
    const int n4 = BB * CC * HH * WW / 4;
    if (i < n4) {
        float4 v = ((const float4*)x)[i];
        v.x = sigmoidf(v.x);
        v.y = sigmoidf(v.y);
        v.z = sigmoidf(v.z);
        v.w = sigmoidf(v.w);
        ((float4*)g_sig)[i] = v;
    }
}

// Input t = 4*l + j maps to (q = t/9, k = t%9, ky = k/3, kx = k%3).
// tile stride: q*10*18, row*18, col. All compile-time after unroll.
#define XIN(t) tbase[((t) / 9) * 180 + (((t) % 9) / 3) * 18 + ((t) % 9) % 3]

// Block = (quarter, bb, o): 8 rows x 32 cols, 128 threads, 2 pixels each
// (cols c and c+16 packed in a f32x2 lane pair).
//
// ws2 (u64 = dup float pair) layout:
//  [0..287]    w0: 18 luts x 16 (8 base + 8 diff)
//  [288..351]  w1 tables 0..3
//  [352..367]  w2 table 0                       (lut index 22)
//  [368..371]  folded w1 t4 bilinear {b0,b1,d0,d1}
//  [372..375]  folded w3 bilinear    {b0,b1,d0,d1}
//  [376..377]  folded w2 t1 linear   {b, d}
__global__ __launch_bounds__(128, 6) void lut_kernel(
    const float* __restrict__ w0, const float* __restrict__ w1,
    const float* __restrict__ w2, const float* __restrict__ w3,
    const int* __restrict__ ci, float* __restrict__ out)
{
    __shared__ u64 tilep[QQ][10][18];   // (col j-1, col j+15) pairs, rows row0-1..row0+8
    __shared__ u64 ws2[384];
    __shared__ int ch[QQ];

    const int quarter = blockIdx.x;
    const int bb = blockIdx.y;
    const int o = blockIdx.z;
    const int tid = threadIdx.x;

    if (tid < QQ) ch[tid] = ci[o * QQ + tid];

    // Full luts: base + precomputed bit3-diffs, duplicated into pairs.
    for (int idx = tid; idx < 368; idx += 128) {
        const int l = idx >> 4, j = idx & 15;
        const float* src;
        if (l < 18)      src = w0 + o * 288 + l * 16;
        else if (l < 22) src = w1 + o * 80 + (l - 18) * 16;
        else             src = w2 + o * 32;
        float v = (j < 8) ? src[j] : (src[j] - src[j - 8]);
        ws2[idx] = pack2(v, v);
    }
    // Folded tables (0.5-pinned inputs averaged out), disjoint slots.
    if (tid == 0) {            // w1 table 4: avg bits 2,3 -> bilinear(b0,b1 / d0,d1)
        const float* s = w1 + o * 80 + 64;
        float cb0 = 0.25f * (s[0] + s[4] + s[8]  + s[12]);
        float cb1 = 0.25f * (s[1] + s[5] + s[9]  + s[13]);
        float cb2 = 0.25f * (s[2] + s[6] + s[10] + s[14]);
        float cb3 = 0.25f * (s[3] + s[7] + s[11] + s[15]);
        ws2[368] = pack2(cb0, cb0); ws2[369] = pack2(cb1, cb1);
        ws2[370] = pack2(cb2 - cb0, cb2 - cb0); ws2[371] = pack2(cb3 - cb1, cb3 - cb1);
    } else if (tid == 1) {     // w3: avg bits 2,3 -> bilinear
        const float* s = w3 + o * 16;
        float cb0 = 0.25f * (s[0] + s[4] + s[8]  + s[12]);
        float cb1 = 0.25f * (s[1] + s[5] + s[9]  + s[13]);
        float cb2 = 0.25f * (s[2] + s[6] + s[10] + s[14]);
        float cb3 = 0.25f * (s[3] + s[7] + s[11] + s[15]);
        ws2[372] = pack2(cb0, cb0); ws2[373] = pack2(cb1, cb1);
        ws2[374] = pack2(cb2 - cb0, cb2 - cb0); ws2[375] = pack2(cb3 - cb1, cb3 - cb1);
    } else if (tid == 2) {     // w2 table 1: avg bits 1,2,3 -> linear
        const float* s = w2 + o * 32 + 16;
        float c0 = 0.f, c1 = 0.f;
        #pragma unroll
        for (int k = 0; k < 8; k++) { c0 += s[2 * k]; c1 += s[2 * k + 1]; }
        c0 *= 0.125f; c1 *= 0.125f;
        ws2[376] = pack2(c0, c0); ws2[377] = pack2(c1 - c0, c1 - c0);
    }
    __syncthreads();

    const int row0 = quarter * 8;
    // Fill paired tile: slot j holds (col j-1, col j+15); OOB -> sigmoid(0)=0.5
    for (int idx = tid; idx < QQ * 10 * 18; idx += 128) {
        int q = idx / 180;
        int rem = idx - q * 180;
        int r = rem / 18;
        int j = rem - r * 18;
        int gh = row0 - 1 + r;
        int cA = j - 1, cB = j + 15;
        float vA = 0.5f, vB = 0.5f;
        if (gh >= 0 && gh < HH) {
            const float* rowp = g_sig + ((bb * CC + ch[q]) * HH + gh) * WW;
            if (cA >= 0)  vA = rowp[cA];
            if (cB < WW)  vB = rowp[cB];
        }
        tilep[q][r][j] = pack2(vA, vB);
    }
    __syncthreads();

    const int lh = tid >> 4;          // 0..7
    const int c  = tid & 15;          // pair cols (c, c+16)
    const u64* tbase = &tilep[0][lh][c];

    // Levels 0+1 interleaved to bound live registers.
    u64 n1[5];
    #pragma unroll
    for (int l1 = 0; l1 < 4; l1++) {
        u64 xs[4];
        #pragma unroll
        for (int j = 0; j < 4; j++) {
            const int l = 4 * l1 + j;
            xs[j] = sig2(lut4p(&ws2[l * 16],
                               XIN(4 * l + 0), XIN(4 * l + 1),
                               XIN(4 * l + 2), XIN(4 * l + 3)));
        }
        n1[l1] = sig2(lut4p(&ws2[(18 + l1) * 16], xs[0], xs[1], xs[2], xs[3]));
    }
    {
        u64 a = sig2(lut4p(&ws2[16 * 16], XIN(64), XIN(65), XIN(66), XIN(67)));
        u64 b = sig2(lut4p(&ws2[17 * 16], XIN(68), XIN(69), XIN(70), XIN(71)));
        // folded w1 t4 bilinear: bit0 = a (cur16), bit1 = b (cur17)
        u64 t0 = fma2(b, ws2[370], ws2[368]);
        u64 t1 = fma2(b, ws2[371], ws2[369]);
        n1[4] = sig2(fma2(a, sub2(t1, t0), t0));
    }

    // Level 2
    u64 n20 = sig2(lut4p(&ws2[22 * 16], n1[0], n1[1], n1[2], n1[3]));
    u64 n21 = sig2(fma2(n1[4], ws2[377], ws2[376]));

    // Level 3: folded w3 bilinear (bit0 = n20, bit1 = n21), no sigmoid
    u64 t0 = fma2(n21, ws2[374], ws2[372]);
    u64 t1 = fma2(n21, ws2[375], ws2[373]);
    u64 res = fma2(n20, sub2(t1, t0), t0);

    float2 r = unpack2(res);
    float* op = out + ((bb * OO + o) * HH + row0 + lh) * WW;
    op[c] = r.x;
    op[c + 16] = r.y;
}

extern "C" void kernel_launch(void* const* d_in, const int* in_sizes, int n_in,
                              void* d_out, int out_size) {
    const float* x  = (const float*)d_in[0];
    const float* w0 = (const float*)d_in[1];
    const float* w1 = (const float*)d_in[2];
    const float* w2 = (const float*)d_in[3];
    const float* w3 = (const float*)d_in[4];
    const int*   ci = (const int*)d_in[5];
    float* out = (float*)d_out;

    const int n4 = BB * CC * HH * WW / 4;  // 131072
    sigmoid_kernel<<<(n4 + 255) / 256, 256>>>(x);
    lut_kernel<<<dim3(4, BB, OO), 128>>>(w0, w1, w2, w3, ci, out);
}

// round 9
// speedup vs baseline: 1.1108x; 1.1108x over previous
#include <cuda_runtime.h>

typedef unsigned long long u64;

// Shapes (fixed by the problem)
#define BB 8
#define CC 64
#define HH 32
#define WW 32
#define OO 32
#define QQ 8

__device__ __forceinline__ float sigmoidf(float x) {
    return __fdividef(1.0f, 1.0f + __expf(-x));
}

// ---- packed f32x2 helpers (Blackwell FFMA2 path, PTX-only) ----
__device__ __forceinline__ u64 fma2(u64 a, u64 b, u64 c) {
    u64 d; asm("fma.rn.f32x2 %0, %1, %2, %3;" : "=l"(d) : "l"(a), "l"(b), "l"(c)); return d;
}
__device__ __forceinline__ u64 sub2(u64 a, u64 b) {
    u64 d; asm("sub.rn.f32x2 %0, %1, %2;" : "=l"(d) : "l"(a), "l"(b)); return d;
}
__device__ __forceinline__ u64 pack2(float lo, float hi) {
    u64 r; asm("mov.b64 %0, {%1, %2};" : "=l"(r) : "f"(lo), "f"(hi)); return r;
}
__device__ __forceinline__ float2 unpack2(u64 v) {
    float2 f; asm("mov.b64 {%0, %1}, %2;" : "=f"(f.x), "=f"(f.y) : "l"(v)); return f;
}
__device__ __forceinline__ u64 sig2(u64 v) {
    float2 f = unpack2(v);
    return pack2(sigmoidf(f.x), sigmoidf(f.y));
}

// Packed 4-input multilinear LUT. w: 16 u64 entries, [0..7]=dup(base corners
// bits 0..2), [8..15]=dup(diff = w[j+8]-w[j]). Reduces bit3,2,1,0.
// ulonglong2 reads force LDS.128 on the broadcast weight loads.
__device__ __forceinline__ u64 lut4p(const u64* __restrict__ w,
                                     u64 x0, u64 x1, u64 x2, u64 x3) {
    const ulonglong2* wv = (const ulonglong2*)w;
    ulonglong2 w01 = wv[0], w23 = wv[1], w45 = wv[2], w67 = wv[3];
    ulonglong2 d01 = wv[4], d23 = wv[5], d45 = wv[6], d67 = wv[7];
    u64 v0 = fma2(x3, d01.x, w01.x);
    u64 v1 = fma2(x3, d01.y, w01.y);
    u64 v2 = fma2(x3, d23.x, w23.x);
    u64 v3 = fma2(x3, d23.y, w23.y);
    u64 v4 = fma2(x3, d45.x, w45.x);
    u64 v5 = fma2(x3, d45.y, w45.y);
    u64 v6 = fma2(x3, d67.x, w67.x);
    u64 v7 = fma2(x3, d67.y, w67.y);
    u64 u0 = fma2(x2, sub2(v4, v0), v0);
    u64 u1 = fma2(x2, sub2(v5, v1), v1);
    u64 u2 = fma2(x2, sub2(v6, v2), v2);
    u64 u3 = fma2(x2, sub2(v7, v3), v3);
    u64 t0 = fma2(x1, sub2(u2, u0), u0);
    u64 t1 = fma2(x1, sub2(u3, u1), u1);
    return fma2(x0, sub2(t1, t0), t0);
}

// Input t = 4*l + j maps to (q = t/9, k = t%9, ky = k/3, kx = k%3).
// tile stride: q*10*18, row*18, col. All compile-time after unroll.
#define XIN(t) tbase[((t) / 9) * 180 + (((t) % 9) / 3) * 18 + ((t) % 9) % 3]

// Block = (quarter, bb, o): 8 rows x 32 cols, 128 threads, 2 pixels each
// (cols c and c+16 packed in a f32x2 lane pair). 7 CTAs/SM = single wave.
//
// ws2 (u64 = dup float pair) layout:
//  [0..287]    w0: 18 luts x 16 (8 base + 8 diff)
//  [288..351]  w1 tables 0..3
//  [352..367]  w2 table 0                       (lut index 22)
//  [368..371]  folded w1 t4 bilinear {b0,b1,d0,d1}
//  [372..375]  folded w3 bilinear    {b0,b1,d0,d1}
//  [376..377]  folded w2 t1 linear   {b, d}
__global__ __launch_bounds__(128, 7) void lut_kernel(
    const float* __restrict__ x,
    const float* __restrict__ w0, const float* __restrict__ w1,
    const float* __restrict__ w2, const float* __restrict__ w3,
    const int* __restrict__ ci, float* __restrict__ out)
{
    __shared__ u64 tilep[QQ][10][18];   // (col j-1, col j+15) pairs, rows row0-1..row0+8
    __shared__ __align__(16) u64 ws2[384];
    __shared__ int ch[QQ];

    const int quarter = blockIdx.x;
    const int bb = blockIdx.y;
    const int o = blockIdx.z;
    const int tid = threadIdx.x;

    if (tid < QQ) ch[tid] = ci[o * QQ + tid];

    // Full luts: base + precomputed bit3-diffs, duplicated into pairs.
    for (int idx = tid; idx < 368; idx += 128) {
        const int l = idx >> 4, j = idx & 15;
        const float* src;
        if (l < 18)      src = w0 + o * 288 + l * 16;
        else if (l < 22) src = w1 + o * 80 + (l - 18) * 16;
        else             src = w2 + o * 32;
        float v = (j < 8) ? src[j] : (src[j] - src[j - 8]);
        ws2[idx] = pack2(v, v);
    }
    // Folded tables (0.5-pinned inputs averaged out), disjoint slots.
    if (tid == 0) {            // w1 table 4: avg bits 2,3 -> bilinear(b0,b1 / d0,d1)
        const float* s = w1 + o * 80 + 64;
        float cb0 = 0.25f * (s[0] + s[4] + s[8]  + s[12]);
        float cb1 = 0.25f * (s[1] + s[5] + s[9]  + s[13]);
        float cb2 = 0.25f * (s[2] + s[6] + s[10] + s[14]);
        float cb3 = 0.25f * (s[3] + s[7] + s[11] + s[15]);
        ws2[368] = pack2(cb0, cb0); ws2[369] = pack2(cb1, cb1);
        ws2[370] = pack2(cb2 - cb0, cb2 - cb0); ws2[371] = pack2(cb3 - cb1, cb3 - cb1);
    } else if (tid == 1) {     // w3: avg bits 2,3 -> bilinear
        const float* s = w3 + o * 16;
        float cb0 = 0.25f * (s[0] + s[4] + s[8]  + s[12]);
        float cb1 = 0.25f * (s[1] + s[5] + s[9]  + s[13]);
        float cb2 = 0.25f * (s[2] + s[6] + s[10] + s[14]);
        float cb3 = 0.25f * (s[3] + s[7] + s[11] + s[15]);
        ws2[372] = pack2(cb0, cb0); ws2[373] = pack2(cb1, cb1);
        ws2[374] = pack2(cb2 - cb0, cb2 - cb0); ws2[375] = pack2(cb3 - cb1, cb3 - cb1);
    } else if (tid == 2) {     // w2 table 1: avg bits 1,2,3 -> linear
        const float* s = w2 + o * 32 + 16;
        float c0 = 0.f, c1 = 0.f;
        #pragma unroll
        for (int k = 0; k < 8; k++) { c0 += s[2 * k]; c1 += s[2 * k + 1]; }
        c0 *= 0.125f; c1 *= 0.125f;
        ws2[376] = pack2(c0, c0); ws2[377] = pack2(c1 - c0, c1 - c0);
    }
    __syncthreads();

    const int row0 = quarter * 8;
    // Fill paired tile straight from x with fused sigmoid.
    // Slot j holds (col j-1, col j+15); OOB -> sigmoid(0) = 0.5
    for (int idx = tid; idx < QQ * 10 * 18; idx += 128) {
        int q = idx / 180;
        int rem = idx - q * 180;
        int r = rem / 18;
        int j = rem - r * 18;
        int gh = row0 - 1 + r;
        int cA = j - 1, cB = j + 15;
        float vA = 0.5f, vB = 0.5f;
        if (gh >= 0 && gh < HH) {
            const float* rowp = x + ((bb * CC + ch[q]) * HH + gh) * WW;
            if (cA >= 0)  vA = sigmoidf(rowp[cA]);
            if (cB < WW)  vB = sigmoidf(rowp[cB]);
        }
        tilep[q][r][j] = pack2(vA, vB);
    }
    __syncthreads();

    const int lh = tid >> 4;          // 0..7
    const int c  = tid & 15;          // pair cols (c, c+16)
    const u64* tbase = &tilep[0][lh][c];

    // Levels 0+1 interleaved to bound live registers.
    u64 n1[5];
    #pragma unroll
    for (int l1 = 0; l1 < 4; l1++) {
        u64 xs[4];
        #pragma unroll
        for (int j = 0; j < 4; j++) {
            const int l = 4 * l1 + j;
            xs[j] = sig2(lut4p(&ws2[l * 16],
                               XIN(4 * l + 0), XIN(4 * l + 1),
                               XIN(4 * l + 2), XIN(4 * l + 3)));
        }
        n1[l1] = sig2(lut4p(&ws2[(18 + l1) * 16], xs[0], xs[1], xs[2], xs[3]));
    }
    {
        u64 a = sig2(lut4p(&ws2[16 * 16], XIN(64), XIN(65), XIN(66), XIN(67)));
        u64 b = sig2(lut4p(&ws2[17 * 16], XIN(68), XIN(69), XIN(70), XIN(71)));
        // folded w1 t4 bilinear: bit0 = a (cur16), bit1 = b (cur17)
        u64 t0 = fma2(b, ws2[370], ws2[368]);
        u64 t1 = fma2(b, ws2[371], ws2[369]);
        n1[4] = sig2(fma2(a, sub2(t1, t0), t0));
    }

    // Level 2
    u64 n20 = sig2(lut4p(&ws2[22 * 16], n1[0], n1[1], n1[2], n1[3]));
    u64 n21 = sig2(fma2(n1[4], ws2[377], ws2[376]));

    // Level 3: folded w3 bilinear (bit0 = n20, bit1 = n21), no sigmoid
    u64 t0 = fma2(n21, ws2[374], ws2[372]);
    u64 t1 = fma2(n21, ws2[375], ws2[373]);
    u64 res = fma2(n20, sub2(t1, t0), t0);

    float2 r = unpack2(res);
    float* op = out + ((bb * OO + o) * HH + row0 + lh) * WW;
    op[c] = r.x;
    op[c + 16] = r.y;
}

extern "C" void kernel_launch(void* const* d_in, const int* in_sizes, int n_in,
                              void* d_out, int out_size) {
    const float* x  = (const float*)d_in[0];
    const float* w0 = (const float*)d_in[1];
    const float* w1 = (const float*)d_in[2];
    const float* w2 = (const float*)d_in[3];
    const float* w3 = (const float*)d_in[4];
    const int*   ci = (const int*)d_in[5];
    float* out = (float*)d_out;

    lut_kernel<<<dim3(4, BB, OO), 128>>>(x, w0, w1, w2, w3, ci, out);
}

// round 11
// speedup vs baseline: 1.1803x; 1.0626x over previous
#include <cuda_runtime.h>

typedef unsigned long long u64;

// Shapes (fixed by the problem)
#define BB 8
#define CC 64
#define HH 32
#define WW 32
#define OO 32
#define QQ 8

// HW tanh sigmoid: sigmoid(x) = 0.5*tanh(0.5x) + 0.5  (MUFU.TANH, sm_75+)
__device__ __forceinline__ float sigmoidf(float x) {
    float t;
    asm("tanh.approx.f32 %0, %1;" : "=f"(t) : "f"(0.5f * x));
    return fmaf(0.5f, t, 0.5f);
}

// ---- packed f32x2 helpers (Blackwell FFMA2 path, PTX-only) ----
__device__ __forceinline__ u64 fma2(u64 a, u64 b, u64 c) {
    u64 d; asm("fma.rn.f32x2 %0, %1, %2, %3;" : "=l"(d) : "l"(a), "l"(b), "l"(c)); return d;
}
__device__ __forceinline__ u64 sub2(u64 a, u64 b) {
    u64 d; asm("sub.rn.f32x2 %0, %1, %2;" : "=l"(d) : "l"(a), "l"(b)); return d;
}
__device__ __forceinline__ u64 pack2(float lo, float hi) {
    u64 r; asm("mov.b64 %0, {%1, %2};" : "=l"(r) : "f"(lo), "f"(hi)); return r;
}
__device__ __forceinline__ float2 unpack2(u64 v) {
    float2 f; asm("mov.b64 {%0, %1}, %2;" : "=f"(f.x), "=f"(f.y) : "l"(v)); return f;
}
// Packed sigmoid: mul2 + 2x MUFU.TANH + fma2 (4 instrs vs 10 for exp/rcp path)
__device__ __forceinline__ u64 sig2(u64 v) {
    const u64 HALF2 = 0x3F0000003F000000ull;  // (0.5f, 0.5f)
    u64 h; asm("mul.rn.f32x2 %0, %1, %2;" : "=l"(h) : "l"(v), "l"(HALF2));
    float2 f = unpack2(h);
    float t0, t1;
    asm("tanh.approx.f32 %0, %1;" : "=f"(t0) : "f"(f.x));
    asm("tanh.approx.f32 %0, %1;" : "=f"(t1) : "f"(f.y));
    return fma2(pack2(t0, t1), HALF2, HALF2);
}

// Packed 4-input multilinear LUT. w: 16 u64 entries, [0..7]=dup(base corners
// bits 0..2), [8..15]=dup(diff = w[j+8]-w[j]). Reduces bit3,2,1,0.
// ulonglong2 reads force LDS.128 on the broadcast weight loads.
__device__ __forceinline__ u64 lut4p(const u64* __restrict__ w,
                                     u64 x0, u64 x1, u64 x2, u64 x3) {
    const ulonglong2* wv = (const ulonglong2*)w;
    ulonglong2 w01 = wv[0], w23 = wv[1], w45 = wv[2], w67 = wv[3];
    ulonglong2 d01 = wv[4], d23 = wv[5], d45 = wv[6], d67 = wv[7];
    u64 v0 = fma2(x3, d01.x, w01.x);
    u64 v1 = fma2(x3, d01.y, w01.y);
    u64 v2 = fma2(x3, d23.x, w23.x);
    u64 v3 = fma2(x3, d23.y, w23.y);
    u64 v4 = fma2(x3, d45.x, w45.x);
    u64 v5 = fma2(x3, d45.y, w45.y);
    u64 v6 = fma2(x3, d67.x, w67.x);
    u64 v7 = fma2(x3, d67.y, w67.y);
    u64 u0 = fma2(x2, sub2(v4, v0), v0);
    u64 u1 = fma2(x2, sub2(v5, v1), v1);
    u64 u2 = fma2(x2, sub2(v6, v2), v2);
    u64 u3 = fma2(x2, sub2(v7, v3), v3);
    u64 t0 = fma2(x1, sub2(u2, u0), u0);
    u64 t1 = fma2(x1, sub2(u3, u1), u1);
    return fma2(x0, sub2(t1, t0), t0);
}

// Input t = 4*l + j maps to (q = t/9, k = t%9, ky = k/3, kx = k%3).
// tile stride: q*10*18, row*18, col. All compile-time after unroll.
#define XIN(t) tbase[((t) / 9) * 180 + (((t) % 9) / 3) * 18 + ((t) % 9) % 3]

// Block = (quarter, bb, o): 8 rows x 32 cols, 128 threads, 2 pixels each
// (cols c and c+16 packed in a f32x2 lane pair). 7 CTAs/SM = single wave.
//
// ws2 (u64 = dup float pair) layout:
//  [0..287]    w0: 18 luts x 16 (8 base + 8 diff)
//  [288..351]  w1 tables 0..3
//  [352..367]  w2 table 0                       (lut index 22)
//  [368..371]  folded w1 t4 bilinear {b0,b1,d0,d1}
//  [372..375]  folded w3 bilinear    {b0,b1,d0,d1}
//  [376..377]  folded w2 t1 linear   {b, d}
__global__ __launch_bounds__(128, 7) void lut_kernel(
    const float* __restrict__ x,
    const float* __restrict__ w0, const float* __restrict__ w1,
    const float* __restrict__ w2, const float* __restrict__ w3,
    const int* __restrict__ ci, float* __restrict__ out)
{
    __shared__ u64 tilep[QQ][10][18];   // (col j-1, col j+15) pairs, rows row0-1..row0+8
    __shared__ __align__(16) u64 ws2[384];
    __shared__ int ch[QQ];

    const int quarter = blockIdx.x;
    const int bb = blockIdx.y;
    const int o = blockIdx.z;
    const int tid = threadIdx.x;

    if (tid < QQ) ch[tid] = ci[o * QQ + tid];

    // Full luts: base + precomputed bit3-diffs, duplicated into pairs.
    for (int idx = tid; idx < 368; idx += 128) {
        const int l = idx >> 4, j = idx & 15;
        const float* src;
        if (l < 18)      src = w0 + o * 288 + l * 16;
        else if (l < 22) src = w1 + o * 80 + (l - 18) * 16;
        else             src = w2 + o * 32;
        float v = (j < 8) ? src[j] : (src[j] - src[j - 8]);
        ws2[idx] = pack2(v, v);
    }
    // Folded tables (0.5-pinned inputs averaged out), disjoint slots.
    if (tid == 0) {            // w1 table 4: avg bits 2,3 -> bilinear(b0,b1 / d0,d1)
        const float* s = w1 + o * 80 + 64;
        float cb0 = 0.25f * (s[0] + s[4] + s[8]  + s[12]);
        float cb1 = 0.25f * (s[1] + s[5] + s[9]  + s[13]);
        float cb2 = 0.25f * (s[2] + s[6] + s[10] + s[14]);
        float cb3 = 0.25f * (s[3] + s[7] + s[11] + s[15]);
        ws2[368] = pack2(cb0, cb0); ws2[369] = pack2(cb1, cb1);
        ws2[370] = pack2(cb2 - cb0, cb2 - cb0); ws2[371] = pack2(cb3 - cb1, cb3 - cb1);
    } else if (tid == 1) {     // w3: avg bits 2,3 -> bilinear
        const float* s = w3 + o * 16;
        float cb0 = 0.25f * (s[0] + s[4] + s[8]  + s[12]);
        float cb1 = 0.25f * (s[1] + s[5] + s[9]  + s[13]);
        float cb2 = 0.25f * (s[2] + s[6] + s[10] + s[14]);
        float cb3 = 0.25f * (s[3] + s[7] + s[11] + s[15]);
        ws2[372] = pack2(cb0, cb0); ws2[373] = pack2(cb1, cb1);
        ws2[374] = pack2(cb2 - cb0, cb2 - cb0); ws2[375] = pack2(cb3 - cb1, cb3 - cb1);
    } else if (tid == 2) {     // w2 table 1: avg bits 1,2,3 -> linear
        const float* s = w2 + o * 32 + 16;
        float c0 = 0.f, c1 = 0.f;
        #pragma unroll
        for (int k = 0; k < 8; k++) { c0 += s[2 * k]; c1 += s[2 * k + 1]; }
        c0 *= 0.125f; c1 *= 0.125f;
        ws2[376] = pack2(c0, c0); ws2[377] = pack2(c1 - c0, c1 - c0);
    }
    __syncthreads();

    const int row0 = quarter * 8;
    // Fill paired tile straight from x with fused sigmoid.
    // Slot j holds (col j-1, col j+15); OOB -> sigmoid(0) = 0.5
    for (int idx = tid; idx < QQ * 10 * 18; idx += 128) {
        int q = idx / 180;
        int rem = idx - q * 180;
        int r = rem / 18;
        int j = rem - r * 18;
        int gh = row0 - 1 + r;
        int cA = j - 1, cB = j + 15;
        float vA = 0.5f, vB = 0.5f;
        if (gh >= 0 && gh < HH) {
            const float* rowp = x + ((bb * CC + ch[q]) * HH + gh) * WW;
            if (cA >= 0)  vA = sigmoidf(rowp[cA]);
            if (cB < WW)  vB = sigmoidf(rowp[cB]);
        }
        tilep[q][r][j] = pack2(vA, vB);
    }
    __syncthreads();

    const int lh = tid >> 4;          // 0..7
    const int c  = tid & 15;          // pair cols (c, c+16)
    const u64* tbase = &tilep[0][lh][c];

    // Levels 0+1 interleaved to bound live registers.
    u64 n1[5];
    #pragma unroll
    for (int l1 = 0; l1 < 4; l1++) {
        u64 xs[4];
        #pragma unroll
        for (int j = 0; j < 4; j++) {
            const int l = 4 * l1 + j;
            xs[j] = sig2(lut4p(&ws2[l * 16],
                               XIN(4 * l + 0), XIN(4 * l + 1),
                               XIN(4 * l + 2), XIN(4 * l + 3)));
        }
        n1[l1] = sig2(lut4p(&ws2[(18 + l1) * 16], xs[0], xs[1], xs[2], xs[3]));
    }
    {
        u64 a = sig2(lut4p(&ws2[16 * 16], XIN(64), XIN(65), XIN(66), XIN(67)));
        u64 b = sig2(lut4p(&ws2[17 * 16], XIN(68), XIN(69), XIN(70), XIN(71)));
        // folded w1 t4 bilinear: bit0 = a (cur16), bit1 = b (cur17)
        u64 t0 = fma2(b, ws2[370], ws2[368]);
        u64 t1 = fma2(b, ws2[371], ws2[369]);
        n1[4] = sig2(fma2(a, sub2(t1, t0), t0));
    }

    // Level 2
    u64 n20 = sig2(lut4p(&ws2[22 * 16], n1[0], n1[1], n1[2], n1[3]));
    u64 n21 = sig2(fma2(n1[4], ws2[377], ws2[376]));

    // Level 3: folded w3 bilinear (bit0 = n20, bit1 = n21), no sigmoid
    u64 t0 = fma2(n21, ws2[374], ws2[372]);
    u64 t1 = fma2(n21, ws2[375], ws2[373]);
    u64 res = fma2(n20, sub2(t1, t0), t0);

    float2 r = unpack2(res);
    float* op = out + ((bb * OO + o) * HH + row0 + lh) * WW;
    op[c] = r.x;
    op[c + 16] = r.y;
}

extern "C" void kernel_launch(void* const* d_in, const int* in_sizes, int n_in,
                              void* d_out, int out_size) {
    const float* x  = (const float*)d_in[0];
    const float* w0 = (const float*)d_in[1];
    const float* w1 = (const float*)d_in[2];
    const float* w2 = (const float*)d_in[3];
    const float* w3 = (const float*)d_in[4];
    const int*   ci = (const int*)d_in[5];
    float* out = (float*)d_out;

    lut_kernel<<<dim3(4, BB, OO), 128>>>(x, w0, w1, w2, w3, ci, out);
}

// round 13
// speedup vs baseline: 1.2073x; 1.0229x over previous
#include <cuda_runtime.h>

typedef unsigned long long u64;

// Shapes (fixed by the problem)
#define BB 8
#define CC 64
#define HH 32
#define WW 32
#define OO 32
#define QQ 8

// HW tanh sigmoid: sigmoid(x) = 0.5*tanh(0.5x) + 0.5  (MUFU.TANH, sm_75+)
__device__ __forceinline__ float sigmoidf(float x) {
    float t;
    asm("tanh.approx.f32 %0, %1;" : "=f"(t) : "f"(0.5f * x));
    return fmaf(0.5f, t, 0.5f);
}

// ---- packed f32x2 helpers (Blackwell FFMA2 path, PTX-only) ----
__device__ __forceinline__ u64 fma2(u64 a, u64 b, u64 c) {
    u64 d; asm("fma.rn.f32x2 %0, %1, %2, %3;" : "=l"(d) : "l"(a), "l"(b), "l"(c)); return d;
}
__device__ __forceinline__ u64 sub2(u64 a, u64 b) {
    u64 d; asm("sub.rn.f32x2 %0, %1, %2;" : "=l"(d) : "l"(a), "l"(b)); return d;
}
__device__ __forceinline__ u64 pack2(float lo, float hi) {
    u64 r; asm("mov.b64 %0, {%1, %2};" : "=l"(r) : "f"(lo), "f"(hi)); return r;
}
__device__ __forceinline__ float2 unpack2(u64 v) {
    float2 f; asm("mov.b64 {%0, %1}, %2;" : "=f"(f.x), "=f"(f.y) : "l"(v)); return f;
}
// Packed sigmoid: mul2 + 2x MUFU.TANH + fma2
__device__ __forceinline__ u64 sig2(u64 v) {
    const u64 HALF2 = 0x3F0000003F000000ull;  // (0.5f, 0.5f)
    u64 h; asm("mul.rn.f32x2 %0, %1, %2;" : "=l"(h) : "l"(v), "l"(HALF2));
    float2 f = unpack2(h);
    float t0, t1;
    asm("tanh.approx.f32 %0, %1;" : "=f"(t0) : "f"(f.x));
    asm("tanh.approx.f32 %0, %1;" : "=f"(t1) : "f"(f.y));
    return fma2(pack2(t0, t1), HALF2, HALF2);
}

// Packed 4-input multilinear LUT, bilinear-coefficient form.
// w: 16 u64 (dup-pair): [a0..a3, b0..b3, c0..c3, d0..d3] for corners k of
// (bit1,bit0), where u_k(x2,x3) = a + x2*b + x3*c + x2*x3*d.
// u_k = fma(x3, fma(x2,d,c), fma(x2,b,a)) — 12 fma, then bits 1,0: 6 ops.
__device__ __forceinline__ u64 lut4p(const u64* __restrict__ w,
                                     u64 x0, u64 x1, u64 x2, u64 x3) {
    const ulonglong2* wv = (const ulonglong2*)w;
    ulonglong2 a01 = wv[0], a23 = wv[1], b01 = wv[2], b23 = wv[3];
    ulonglong2 c01 = wv[4], c23 = wv[5], d01 = wv[6], d23 = wv[7];
    u64 u0 = fma2(x3, fma2(x2, d01.x, c01.x), fma2(x2, b01.x, a01.x));
    u64 u1 = fma2(x3, fma2(x2, d01.y, c01.y), fma2(x2, b01.y, a01.y));
    u64 u2 = fma2(x3, fma2(x2, d23.x, c23.x), fma2(x2, b23.x, a23.x));
    u64 u3 = fma2(x3, fma2(x2, d23.y, c23.y), fma2(x2, b23.y, a23.y));
    u64 t0 = fma2(x1, sub2(u2, u0), u0);
    u64 t1 = fma2(x1, sub2(u3, u1), u1);
    return fma2(x0, sub2(t1, t0), t0);
}

// Input t = 4*l + j maps to (q = t/9, k = t%9, ky = k/3, kx = k%3).
// tile stride: q*10*18, row*18, col. All compile-time after unroll.
#define XIN(t) tbase[((t) / 9) * 180 + (((t) % 9) / 3) * 18 + ((t) % 9) % 3]

// Block = (quarter, bb, o): 8 rows x 32 cols, 128 threads, 2 pixels each
// (cols c and c+16 packed in a f32x2 lane pair). 7 CTAs/SM = single wave.
//
// ws2 (u64 = dup float pair) layout:
//  [0..287]    w0: 18 luts x 16 (abcd form)
//  [288..351]  w1 tables 0..3 (abcd form)
//  [352..367]  w2 table 0 (abcd form)          (lut index 22)
//  [368..371]  folded w1 t4 bilinear {A,B,C,D}  (bit0=cur16, bit1=cur17)
//  [372..375]  folded w3 bilinear    {A,B,C,D}  (bit0=n20, bit1=n21)
//  [376..377]  folded w2 t1 linear   {base, diff}
__global__ __launch_bounds__(128, 7) void lut_kernel(
    const float* __restrict__ x,
    const float* __restrict__ w0, const float* __restrict__ w1,
    const float* __restrict__ w2, const float* __restrict__ w3,
    const int* __restrict__ ci, float* __restrict__ out)
{
    __shared__ u64 tilep[QQ][10][18];   // (col j-1, col j+15) pairs, rows row0-1..row0+8
    __shared__ __align__(16) u64 ws2[384];
    __shared__ int ch[QQ];

    const int quarter = blockIdx.x;
    const int bb = blockIdx.y;
    const int o = blockIdx.z;
    const int tid = threadIdx.x;

    if (tid < QQ) ch[tid] = ci[o * QQ + tid];

    // Full luts in abcd (bilinear-coefficient) form, duplicated into pairs.
    for (int idx = tid; idx < 368; idx += 128) {
        const int l = idx >> 4, j = idx & 15;
        const float* src;
        if (l < 18)      src = w0 + o * 288 + l * 16;
        else if (l < 22) src = w1 + o * 80 + (l - 18) * 16;
        else             src = w2 + o * 32;
        const int k = j & 3, g = j >> 2;
        float v;
        if (g == 0)      v = src[k];
        else if (g == 1) v = src[k + 4] - src[k];
        else if (g == 2) v = src[k + 8] - src[k];
        else             v = src[k + 12] - src[k + 8] - src[k + 4] + src[k];
        ws2[idx] = pack2(v, v);
    }
    // Folded tables (0.5-pinned inputs averaged out), disjoint slots.
    if (tid == 0) {            // w1 table 4: avg bits 2,3 -> bilinear abcd
        const float* s = w1 + o * 80 + 64;
        float cb0 = 0.25f * (s[0] + s[4] + s[8]  + s[12]);
        float cb1 = 0.25f * (s[1] + s[5] + s[9]  + s[13]);
        float cb2 = 0.25f * (s[2] + s[6] + s[10] + s[14]);
        float cb3 = 0.25f * (s[3] + s[7] + s[11] + s[15]);
        ws2[368] = pack2(cb0, cb0);
        ws2[369] = pack2(cb1 - cb0, cb1 - cb0);
        ws2[370] = pack2(cb2 - cb0, cb2 - cb0);
        float d = cb3 - cb2 - cb1 + cb0;
        ws2[371] = pack2(d, d);
    } else if (tid == 1) {     // w3: avg bits 2,3 -> bilinear abcd
        const float* s = w3 + o * 16;
        float cb0 = 0.25f * (s[0] + s[4] + s[8]  + s[12]);
        float cb1 = 0.25f * (s[1] + s[5] + s[9]  + s[13]);
        float cb2 = 0.25f * (s[2] + s[6] + s[10] + s[14]);
        float cb3 = 0.25f * (s[3] + s[7] + s[11] + s[15]);
        ws2[372] = pack2(cb0, cb0);
        ws2[373] = pack2(cb1 - cb0, cb1 - cb0);
        ws2[374] = pack2(cb2 - cb0, cb2 - cb0);
        float d = cb3 - cb2 - cb1 + cb0;
        ws2[375] = pack2(d, d);
    } else if (tid == 2) {     // w2 table 1: avg bits 1,2,3 -> linear
        const float* s = w2 + o * 32 + 16;
        float c0 = 0.f, c1 = 0.f;
        #pragma unroll
        for (int k = 0; k < 8; k++) { c0 += s[2 * k]; c1 += s[2 * k + 1]; }
        c0 *= 0.125f; c1 *= 0.125f;
        ws2[376] = pack2(c0, c0); ws2[377] = pack2(c1 - c0, c1 - c0);
    }
    __syncthreads();

    const int row0 = quarter * 8;

    // Fill paired tile, column-walk: thread (fq = tid>>4, fc = tid&15) walks
    // 10 rows of column fc; threads fc=14,15 also cover straggler cols 16,17.
    // Slot [q][r][c] holds (col c-1, col c+15) of row row0-1+r; OOB -> 0.5.
    {
        const int fq = tid >> 4;
        const int fc = tid & 15;
        const float* gb = x + ((bb * CC + ch[fq]) * HH + (row0 - 1)) * WW;
        auto fill_col = [&](int c) {
            const bool okA = (c >= 1);
            const bool okB = (c + 15 < WW);
            const float* pA = gb + (c - 1);
            const float* pB = gb + (c + 15);
            u64* sp = &tilep[fq][0][c];
            #pragma unroll
            for (int r = 0; r < 10; r++) {
                const int gh = row0 - 1 + r;
                const bool okR = ((unsigned)gh < HH);
                float vA = 0.5f, vB = 0.5f;
                if (okA && okR) vA = sigmoidf(pA[r * WW]);
                if (okB && okR) vB = sigmoidf(pB[r * WW]);
                sp[r * 18] = pack2(vA, vB);
            }
        };
        fill_col(fc);
        if (fc >= 14) fill_col(fc + 2);   // cols 16, 17
    }
    __syncthreads();

    const int lh = tid >> 4;          // 0..7
    const int c  = tid & 15;          // pair cols (c, c+16)
    const u64* tbase = &tilep[0][lh][c];

    // Levels 0+1 interleaved to bound live registers.
    u64 n1[5];
    #pragma unroll
    for (int l1 = 0; l1 < 4; l1++) {
        u64 xs[4];
        #pragma unroll
        for (int j = 0; j < 4; j++) {
            const int l = 4 * l1 + j;
            xs[j] = sig2(lut4p(&ws2[l * 16],
                               XIN(4 * l + 0), XIN(4 * l + 1),
                               XIN(4 * l + 2), XIN(4 * l + 3)));
        }
        n1[l1] = sig2(lut4p(&ws2[(18 + l1) * 16], xs[0], xs[1], xs[2], xs[3]));
    }
    {
        u64 a = sig2(lut4p(&ws2[16 * 16], XIN(64), XIN(65), XIN(66), XIN(67)));
        u64 b = sig2(lut4p(&ws2[17 * 16], XIN(68), XIN(69), XIN(70), XIN(71)));
        // folded w1 t4 bilinear abcd: bit0 = a (cur16), bit1 = b (cur17)
        n1[4] = sig2(fma2(b, fma2(a, ws2[371], ws2[370]),
                             fma2(a, ws2[369], ws2[368])));
    }

    // Level 2
    u64 n20 = sig2(lut4p(&ws2[22 * 16], n1[0], n1[1], n1[2], n1[3]));
    u64 n21 = sig2(fma2(n1[4], ws2[377], ws2[376]));

    // Level 3: folded w3 bilinear abcd (bit0 = n20, bit1 = n21), no sigmoid
    u64 res = fma2(n21, fma2(n20, ws2[375], ws2[374]),
                        fma2(n20, ws2[373], ws2[372]));

    float2 r = unpack2(res);
    float* op = out + ((bb * OO + o) * HH + row0 + lh) * WW;
    op[c] = r.x;
    op[c + 16] = r.y;
}

extern "C" void kernel_launch(void* const* d_in, const int* in_sizes, int n_in,
                              void* d_out, int out_size) {
    const float* x  = (const float*)d_in[0];
    const float* w0 = (const float*)d_in[1];
    const float* w1 = (const float*)d_in[2];
    const float* w2 = (const float*)d_in[3];
    const float* w3 = (const float*)d_in[4];
    const int*   ci = (const int*)d_in[5];
    float* out = (float*)d_out;

    lut_kernel<<<dim3(4, BB, OO), 128>>>(x, w0, w1, w2, w3, ci, out);
}